// round 3
// baseline (speedup 1.0000x reference)
#include <cuda_runtime.h>
#include <stdint.h>

// XNOR binarized linear via s8 IMMA (mma.sync m16n8k32).
// y[n,o] = (sum_k sign(x[n,k])*sign(w[o,k])) * scale[o]
// Signs as s8 +/-1, s32 accumulation -> exact integers, then fp32 scale.

constexpr int NROWS  = 262144;
constexpr int DIM    = 256;              // IN == OUT == K
constexpr int TILE_M = 128;
constexpr int NTILES = NROWS / TILE_M;   // 2048

// Padded smem strides (272 = 256 + 16 bytes) -> conflict-free fragment LDS.
constexpr int ASTR = 272;
constexpr int BSTR = 272;
constexpr int SA   = 0;                   // A: 128 x 272  = 34816 B
constexpr int SB   = TILE_M * ASTR;       // B: 256 x 272  = 69632 B
constexpr int SMEM_TOTAL = SB + DIM * BSTR;   // 104448 B

// Packed s8 weights (row-major [256][256]), filled by pre-kernel.
__device__ __align__(16) uint8_t g_ws8[DIM * DIM];

// ---------------------------------------------------------------------------
// sign-pack: 4 floats -> 4 s8 bytes (+1 / -1). (s<<8)-s turns per-byte 0/1
// into 0x00/0xFF (base-256 borrow trick), OR with 0x01 gives 0x01/0xFF.
// ---------------------------------------------------------------------------
__device__ __forceinline__ uint32_t sign4(float4 f) {
    uint32_t s = (__float_as_uint(f.x) >> 31)
               | ((__float_as_uint(f.y) >> 31) << 8)
               | ((__float_as_uint(f.z) >> 31) << 16)
               | ((__float_as_uint(f.w) >> 31) << 24);
    return 0x01010101u | ((s << 8) - s);
}

__global__ void pack_w_kernel(const float* __restrict__ w) {
    int id = blockIdx.x * blockDim.x + threadIdx.x;      // one float4 each
    if (id >= DIM * DIM / 4) return;
    float4 f = reinterpret_cast<const float4*>(w)[id];
    reinterpret_cast<uint32_t*>(g_ws8)[id] = sign4(f);
}

// ---------------------------------------------------------------------------
// Main kernel: 256 threads (8 warps), one M=128 tile per block.
// Warp w -> output rows [16w, 16w+16). A fragments hoisted to registers,
// B fragments streamed from padded smem.
// ---------------------------------------------------------------------------
__global__ void __launch_bounds__(256, 2)
xnor_imma_kernel(const float* __restrict__ x,
                 const float* __restrict__ scale,
                 float* __restrict__ out) {
    extern __shared__ __align__(16) uint8_t smem[];
    const int tid  = threadIdx.x;
    const int warp = tid >> 5;
    const int lane = tid & 31;
    const int q    = lane >> 2;      // 0..7
    const int kq   = (lane & 3) * 4; // 0,4,8,12

    // ---- fill B (weights, s8, padded rows) : 4096 uint4 ----
    {
        const uint4* gw = reinterpret_cast<const uint4*>(g_ws8);
#pragma unroll
        for (int j = 0; j < 16; ++j) {
            int idx = j * 256 + tid;          // 0..4095
            int o   = idx >> 4;               // row
            int k16 = idx & 15;               // 16B chunk
            *reinterpret_cast<uint4*>(smem + SB + o * BSTR + k16 * 16) = gw[idx];
        }
    }

    // ---- fill A (x tile, f32 -> s8, padded rows) : 8192 float4 ----
    {
        const float4* xt = reinterpret_cast<const float4*>(x) +
                           (size_t)blockIdx.x * TILE_M * (DIM / 4);
#pragma unroll 8
        for (int i = 0; i < 32; ++i) {
            int v = i * 256 + tid;            // float4 index, coalesced
            float4 f = xt[v];
            int r  = v >> 6;                  // row 0..127
            int kb = (v & 63) * 4;            // byte offset in row
            *reinterpret_cast<uint32_t*>(smem + SA + r * ASTR + kb) = sign4(f);
        }
    }
    __syncthreads();

    // ---- hoist A fragments: 8 k-steps x 4 regs ----
    uint32_t a[8][4];
    {
        const uint8_t* pa = smem + SA + (warp * 16 + q) * ASTR + kq;
#pragma unroll
        for (int ks = 0; ks < 8; ++ks) {
            a[ks][0] = *reinterpret_cast<const uint32_t*>(pa + ks * 32);
            a[ks][1] = *reinterpret_cast<const uint32_t*>(pa + ks * 32 + 8 * ASTR);
            a[ks][2] = *reinterpret_cast<const uint32_t*>(pa + ks * 32 + 16);
            a[ks][3] = *reinterpret_cast<const uint32_t*>(pa + ks * 32 + 8 * ASTR + 16);
        }
    }

    // ---- compute: 32 n-tiles of 8 cols, K = 8 x 32 ----
    const size_t row0 = (size_t)blockIdx.x * TILE_M + warp * 16 + q;
    const float2* sc2 = reinterpret_cast<const float2*>(scale);
    float* out0 = out + row0 * DIM + (lane & 3) * 2;

#pragma unroll 4
    for (int nt = 0; nt < 32; ++nt) {
        int c0 = 0, c1 = 0, c2 = 0, c3 = 0;
        const uint8_t* pb = smem + SB + (nt * 8 + q) * BSTR + kq;
#pragma unroll
        for (int ks = 0; ks < 8; ++ks) {
            uint32_t b0 = *reinterpret_cast<const uint32_t*>(pb + ks * 32);
            uint32_t b1 = *reinterpret_cast<const uint32_t*>(pb + ks * 32 + 16);
            asm volatile(
                "mma.sync.aligned.m16n8k32.row.col.s32.s8.s8.s32 "
                "{%0,%1,%2,%3}, {%4,%5,%6,%7}, {%8,%9}, {%0,%1,%2,%3};"
                : "+r"(c0), "+r"(c1), "+r"(c2), "+r"(c3)
                : "r"(a[ks][0]), "r"(a[ks][1]), "r"(a[ks][2]), "r"(a[ks][3]),
                  "r"(b0), "r"(b1));
        }
        float2 s = sc2[nt * 4 + (lane & 3)];
        float2 v0 = make_float2((float)c0 * s.x, (float)c1 * s.y);
        float2 v1 = make_float2((float)c2 * s.x, (float)c3 * s.y);
        *reinterpret_cast<float2*>(out0 + nt * 8)             = v0;   // row q
        *reinterpret_cast<float2*>(out0 + nt * 8 + 8 * DIM)   = v1;   // row q+8
    }
}

// ---------------------------------------------------------------------------
// kernel_launch: d_in[0]=x [N,256] f32, d_in[1]=weight [256,256] f32,
//                d_in[2]=scale [1,256] f32; d_out = y [N,256] f32.
// ---------------------------------------------------------------------------
extern "C" void kernel_launch(void* const* d_in, const int* in_sizes, int n_in,
                              void* d_out, int out_size) {
    const float* x      = (const float*)d_in[0];
    const float* weight = (const float*)d_in[1];
    const float* scale  = (const float*)d_in[2];
    float* out          = (float*)d_out;
    (void)in_sizes; (void)n_in; (void)out_size;

    cudaFuncSetAttribute(xnor_imma_kernel,
                         cudaFuncAttributeMaxDynamicSharedMemorySize, SMEM_TOTAL);

    pack_w_kernel<<<64, 256>>>(weight);                         // 16384 float4s
    xnor_imma_kernel<<<NTILES, 256, SMEM_TOTAL>>>(x, scale, out);
}

// round 5
// speedup vs baseline: 1.9280x; 1.9280x over previous
#include <cuda_runtime.h>
#include <stdint.h>

// XNOR binarized linear, warp-broadcast popc version (exact epilogue).
// y[n,o] = (256 - 2*popc(xbits[n] ^ wbits[o])) * scale[o]
// Each warp owns rows and computes ALL 256 outputs for them:
//   - row bits via 8 ballots (every lane receives all 8 words)
//   - lane L handles output columns o = 32j + L, j = 0..7 (weights in regs)
//   - stores coalesced (128B per STG group)
// No shared memory, no __syncthreads in the main kernel.

constexpr int NROWS = 262144;
constexpr int DIM   = 256;   // IN == OUT
constexpr int WPR   = 8;     // packed words per row

constexpr int CHUNK_ROWS = 128;                 // rows per block chunk (4 warps x 32)
constexpr int NCHUNK     = NROWS / CHUNK_ROWS;  // 2048
constexpr int GRID       = 592;                 // 148 SMs x 4 blocks

// Packed weight bits (8 KB), produced by pre-kernel.
__device__ uint32_t g_wbits[DIM * WPR];

// ---------------------------------------------------------------------------
// Pre-kernel: pack weight sign bits (one warp per output row).
// Word (h*4+c), bit L  <->  element h*128 + 4L + c. Matches x packing below.
// ---------------------------------------------------------------------------
__global__ void pack_w_kernel(const float* __restrict__ w) {
    int warp = (blockIdx.x * blockDim.x + threadIdx.x) >> 5;
    int lane = threadIdx.x & 31;
    if (warp >= DIM) return;
    const float4* row = reinterpret_cast<const float4*>(w) + (size_t)warp * (DIM / 4);
#pragma unroll
    for (int h = 0; h < 2; ++h) {
        float4 v = row[h * 32 + lane];
        uint32_t m0 = __ballot_sync(0xFFFFFFFFu, v.x < 0.0f);
        uint32_t m1 = __ballot_sync(0xFFFFFFFFu, v.y < 0.0f);
        uint32_t m2 = __ballot_sync(0xFFFFFFFFu, v.z < 0.0f);
        uint32_t m3 = __ballot_sync(0xFFFFFFFFu, v.w < 0.0f);
        if (lane == 0) {
            *reinterpret_cast<uint4*>(&g_wbits[warp * WPR + h * 4]) =
                make_uint4(m0, m1, m2, m3);
        }
    }
}

// ---------------------------------------------------------------------------
// Main kernel: 128 threads (4 warps), grid-stride over 128-row chunks.
// ---------------------------------------------------------------------------
__global__ void __launch_bounds__(128, 4)
xnor_bcast_kernel(const float* __restrict__ x,
                  const float* __restrict__ scale,
                  float* __restrict__ out) {
    const int warp = threadIdx.x >> 5;
    const int lane = threadIdx.x & 31;

    // Hoist weights + scale for this lane's 8 output columns.
    uint4 wlo[8], whi[8];
    float S[8];
#pragma unroll
    for (int j = 0; j < 8; ++j) {
        int o = j * 32 + lane;
        wlo[j] = *reinterpret_cast<const uint4*>(&g_wbits[o * WPR]);
        whi[j] = *reinterpret_cast<const uint4*>(&g_wbits[o * WPR + 4]);
        S[j] = scale[o];
    }

    // magic constant pre-offset by +256: t = MAGIC256 - 2p  ==  2^23*1.5 + (256-2p)
    constexpr uint32_t MAGIC256 = 0x4B400000u + 256u;

    const float4* x4 = reinterpret_cast<const float4*>(x);

    for (int ch = blockIdx.x; ch < NCHUNK; ch += gridDim.x) {
        const int row0 = ch * CHUNK_ROWS + warp * 32;
        const float4* rp = x4 + (size_t)row0 * (DIM / 4);
        float* orow = out + (size_t)row0 * DIM + lane;

        // prefetch first row
        float4 c0 = rp[lane];
        float4 c1 = rp[32 + lane];

#pragma unroll 2
        for (int r = 0; r < 32; ++r) {
            // prefetch next row (clamped on last iteration)
            const float4* np = rp + (size_t)(r + 1 < 32 ? r + 1 : r) * (DIM / 4);
            float4 n0 = np[lane];
            float4 n1 = np[32 + lane];

            // transpose row signs into 8 words, broadcast to all lanes
            uint32_t b0 = __ballot_sync(0xFFFFFFFFu, c0.x < 0.0f);
            uint32_t b1 = __ballot_sync(0xFFFFFFFFu, c0.y < 0.0f);
            uint32_t b2 = __ballot_sync(0xFFFFFFFFu, c0.z < 0.0f);
            uint32_t b3 = __ballot_sync(0xFFFFFFFFu, c0.w < 0.0f);
            uint32_t b4 = __ballot_sync(0xFFFFFFFFu, c1.x < 0.0f);
            uint32_t b5 = __ballot_sync(0xFFFFFFFFu, c1.y < 0.0f);
            uint32_t b6 = __ballot_sync(0xFFFFFFFFu, c1.z < 0.0f);
            uint32_t b7 = __ballot_sync(0xFFFFFFFFu, c1.w < 0.0f);

            // 8 independent output-group chains (ILP)
#pragma unroll
            for (int j = 0; j < 8; ++j) {
                int p = __popc(b0 ^ wlo[j].x) + __popc(b1 ^ wlo[j].y) +
                        __popc(b2 ^ wlo[j].z) + __popc(b3 ^ wlo[j].w) +
                        __popc(b4 ^ whi[j].x) + __popc(b5 ^ whi[j].y) +
                        __popc(b6 ^ whi[j].z) + __popc(b7 ^ whi[j].w);
                // exact: t = magic + (256-2p); fd = float(256-2p) exactly
                uint32_t t = MAGIC256 - 2u * (uint32_t)p;       // IMAD
                float fd = __uint_as_float(t) - 12582912.0f;    // FADD (exact)
                orow[j * 32] = fd * S[j];                       // FMUL (single round)
            }

            c0 = n0; c1 = n1;
            orow += DIM;
        }
    }
}

// ---------------------------------------------------------------------------
// kernel_launch: d_in[0]=x [N,256] f32, d_in[1]=weight [256,256] f32,
//                d_in[2]=scale [1,256] f32; d_out = y [N,256] f32.
// ---------------------------------------------------------------------------
extern "C" void kernel_launch(void* const* d_in, const int* in_sizes, int n_in,
                              void* d_out, int out_size) {
    const float* x      = (const float*)d_in[0];
    const float* weight = (const float*)d_in[1];
    const float* scale  = (const float*)d_in[2];
    float* out          = (float*)d_out;
    (void)in_sizes; (void)n_in; (void)out_size;

    pack_w_kernel<<<32, 256>>>(weight);
    xnor_bcast_kernel<<<GRID, 128>>>(x, scale, out);
}